// round 5
// baseline (speedup 1.0000x reference)
#include <cuda_runtime.h>

#define N_NODES 100000
#define N_EDGES 1600000
#define F_IN 22
#define F_HID 32

// ---------------- scratch (static device globals; no allocation) ----------
__device__ float g_M1[F_IN * F_HID];
__device__ float g_c1[F_HID];
__device__ float g_M2b[F_IN * F_HID];
__device__ float g_c2b[F_HID];
__device__ float g_Mp[F_IN];
__device__ float g_cp;
__device__ float g_dis[N_NODES];
__device__ int   g_cnt[N_NODES];
__device__ int   g_is64;                 // 1 if edge_index is really int64
__device__ int   g_src[N_EDGES];
__device__ int   g_dst[N_EDGES];
__device__ __align__(16) float g_p1[(size_t)N_NODES * F_HID];
__device__ __align__(16) float g_a1[(size_t)N_NODES * F_HID];
__device__ __align__(16) float g_p2[(size_t)N_NODES * F_HID];
__device__ __align__(16) float g_a2[(size_t)N_NODES * F_HID];

// ---------------- dtype sniff: int64 vs int32 edge_index -------------------
__global__ void __launch_bounds__(256) k_detect(const void* __restrict__ ei)
{
    const long long* p64 = (const long long*)ei;
    int t = threadIdx.x;                          // 256 threads
    long long v = p64[(long long)t * (N_EDGES / 256)];
    int ok = (v >= 0 && v < N_NODES) ? 1 : 0;
    __shared__ int all_ok;
    if (t == 0) all_ok = 1;
    __syncthreads();
    if (!ok) atomicAnd(&all_ok, 0);
    __syncthreads();
    if (t == 0) g_is64 = all_ok;
}

// ---------------- index conversion -> int32 --------------------------------
__global__ void __launch_bounds__(256) k_convert(const void* __restrict__ ei)
{
    int stride = gridDim.x * blockDim.x;
    if (g_is64) {
        const long long* p = (const long long*)ei;
        for (int e = blockIdx.x * blockDim.x + threadIdx.x; e < N_EDGES; e += stride) {
            g_src[e] = (int)p[e];
            g_dst[e] = (int)p[e + N_EDGES];
        }
    } else {
        const int* p = (const int*)ei;
        for (int e = blockIdx.x * blockDim.x + threadIdx.x; e < N_EDGES; e += stride) {
            g_src[e] = p[e];
            g_dst[e] = p[e + N_EDGES];
        }
    }
}

// ---------------- weight fusion (1 block, 256 threads) ---------------------
__global__ void __launch_bounds__(256) k_fuse_weights(
    const float* __restrict__ We,   // [22,32]
    const float* __restrict__ be,   // [32]
    const float* __restrict__ W1,   // [32,32]
    const float* __restrict__ W2,   // [64,32]
    const float* __restrict__ Wp)   // [64,1]
{
    for (int t = threadIdx.x; t < F_IN * F_HID; t += 256) {
        int k = t / F_HID, j = t % F_HID;
        float m1 = 0.f, m2b = 0.f;
        for (int u = 0; u < F_HID; ++u) {
            float we = We[k * F_HID + u];
            m1  += we * W1[u * F_HID + j];
            m2b += we * W2[(F_HID + u) * F_HID + j];
        }
        g_M1[t]  = m1;
        g_M2b[t] = m2b;
    }
    int t = threadIdx.x;
    if (t < F_HID) {
        float c1 = 0.f, c2b = 0.f;
        for (int u = 0; u < F_HID; ++u) {
            c1  += be[u] * W1[u * F_HID + t];
            c2b += be[u] * W2[(F_HID + u) * F_HID + t];
        }
        g_c1[t]  = c1;
        g_c2b[t] = c2b;
    }
    if (t >= 64 && t < 64 + F_IN) {
        int k = t - 64;
        float mp = 0.f;
        for (int u = 0; u < F_HID; ++u)
            mp += We[k * F_HID + u] * Wp[F_HID + u];
        g_Mp[k] = mp;
    }
    if (t == 255) {
        float cp = 0.f;
        for (int u = 0; u < F_HID; ++u) cp += be[u] * Wp[F_HID + u];
        g_cp = cp;
    }
}

// ---------------- degree ---------------------------------------------------
__global__ void __launch_bounds__(256) k_cnt_init()
{
    int i = blockIdx.x * blockDim.x + threadIdx.x;
    if (i < N_NODES) g_cnt[i] = 1;            // self loop
}

__global__ void __launch_bounds__(256) k_count()
{
    int stride = gridDim.x * blockDim.x;
    for (int e = blockIdx.x * blockDim.x + threadIdx.x; e < N_EDGES; e += stride)
        atomicAdd(&g_cnt[g_dst[e]], 1);
}

__global__ void __launch_bounds__(256) k_dis()
{
    int i = blockIdx.x * blockDim.x + threadIdx.x;
    if (i < N_NODES) g_dis[i] = rsqrtf((float)g_cnt[i]);
}

// ---------------- layer-1 node kernel: p1 = dis * (x@M1 + c1) -------------
__global__ void __launch_bounds__(256) k_node1(const float* __restrict__ x)
{
    __shared__ float sM1[F_IN * F_HID];
    __shared__ float sc1[F_HID];
    for (int i = threadIdx.x; i < F_IN * F_HID; i += blockDim.x) sM1[i] = g_M1[i];
    if (threadIdx.x < F_HID) sc1[threadIdx.x] = g_c1[threadIdx.x];
    __syncthreads();

    int lane  = threadIdx.x & 31;
    int warp  = (blockIdx.x * blockDim.x + threadIdx.x) >> 5;
    int nwarp = (gridDim.x * blockDim.x) >> 5;
    for (int n = warp; n < N_NODES; n += nwarp) {
        const float* xr = x + (size_t)n * F_IN;
        float acc = sc1[lane];
        #pragma unroll
        for (int k = 0; k < F_IN; ++k)
            acc += xr[k] * sM1[k * F_HID + lane];          // xr[k] broadcast
        float p = g_dis[n] * acc;
        size_t o = (size_t)n * F_HID + lane;
        g_p1[o] = p;
        g_a1[o] = p;                                       // self-loop init
    }
}

// ---------------- edge scatter: a[dst] += p[src] ---------------------------
// 8 threads/edge: each gathers one float4 (LDG.128) and emits 4 scalar
// atomicAdds (REDG.ADD.F32, no return).
template <int PHASE>
__global__ void __launch_bounds__(256) k_scatter()
{
    const float* __restrict__ p = (PHASE == 0) ? g_p1 : g_p2;
    float* __restrict__ a       = (PHASE == 0) ? g_a1 : g_a2;

    int gt   = blockIdx.x * blockDim.x + threadIdx.x;
    int l    = gt & 7;                      // 8 lanes per edge, float4 each
    int grp  = gt >> 3;
    int ngrp = (gridDim.x * blockDim.x) >> 3;
    for (int e = grp; e < N_EDGES; e += ngrp) {
        int s = g_src[e];
        int d = g_dst[e];
        float4 v = *reinterpret_cast<const float4*>(p + (size_t)s * F_HID + l * 4);
        float* ad = a + (size_t)d * F_HID + l * 4;
        atomicAdd(ad + 0, v.x);
        atomicAdd(ad + 1, v.y);
        atomicAdd(ad + 2, v.z);
        atomicAdd(ad + 3, v.w);
    }
}

// ---------------- layer-2 node kernel --------------------------------------
// r1 = relu(dis*a1 + b1); p2 = dis * (r1@W2[:32] + x@M2b + c2b)
__global__ void __launch_bounds__(256) k_node2(const float* __restrict__ x,
                                               const float* __restrict__ b1,
                                               const float* __restrict__ W2)
{
    __shared__ float sW2t[F_HID * F_HID];
    __shared__ float sM2b[F_IN * F_HID];
    __shared__ float sc2b[F_HID];
    __shared__ float sb1[F_HID];
    for (int i = threadIdx.x; i < F_HID * F_HID; i += blockDim.x) sW2t[i] = W2[i];
    for (int i = threadIdx.x; i < F_IN * F_HID; i += blockDim.x) sM2b[i] = g_M2b[i];
    if (threadIdx.x < F_HID) { sc2b[threadIdx.x] = g_c2b[threadIdx.x];
                               sb1[threadIdx.x]  = b1[threadIdx.x]; }
    __syncthreads();

    int lane  = threadIdx.x & 31;
    int warp  = (blockIdx.x * blockDim.x + threadIdx.x) >> 5;
    int nwarp = (gridDim.x * blockDim.x) >> 5;
    for (int n = warp; n < N_NODES; n += nwarp) {
        float dis = g_dis[n];
        size_t o  = (size_t)n * F_HID + lane;
        float r1  = fmaxf(dis * g_a1[o] + sb1[lane], 0.f);
        const float* xr = x + (size_t)n * F_IN;
        float acc = sc2b[lane];
        #pragma unroll
        for (int k = 0; k < F_IN; ++k)
            acc += xr[k] * sM2b[k * F_HID + lane];
        #pragma unroll
        for (int k = 0; k < F_HID; ++k) {
            float rk = __shfl_sync(0xffffffffu, r1, k);
            acc += rk * sW2t[k * F_HID + lane];
        }
        float p = dis * acc;
        g_p2[o] = p;
        g_a2[o] = p;                                        // self-loop init
    }
}

// ---------------- final kernel ---------------------------------------------
// r2 = relu(dis*a2 + b2); out = relu(r2@Wp[:32] + x@Mp + cp + bp + x[:,1])
__global__ void __launch_bounds__(256) k_final(const float* __restrict__ x,
                                               const float* __restrict__ b2,
                                               const float* __restrict__ Wp,
                                               const float* __restrict__ bp,
                                               float* __restrict__ out)
{
    __shared__ float sb2[F_HID];
    __shared__ float swp[F_HID];
    __shared__ float sMp[F_IN];
    if (threadIdx.x < F_HID) { sb2[threadIdx.x] = b2[threadIdx.x];
                               swp[threadIdx.x] = Wp[threadIdx.x]; }
    if (threadIdx.x < F_IN) sMp[threadIdx.x] = g_Mp[threadIdx.x];
    __syncthreads();

    int lane  = threadIdx.x & 31;
    int warp  = (blockIdx.x * blockDim.x + threadIdx.x) >> 5;
    int nwarp = (gridDim.x * blockDim.x) >> 5;
    float bias = g_cp + bp[0];
    for (int n = warp; n < N_NODES; n += nwarp) {
        float dis = g_dis[n];
        size_t o  = (size_t)n * F_HID + lane;
        float r2  = fmaxf(dis * g_a2[o] + sb2[lane], 0.f);
        const float* xr = x + (size_t)n * F_IN;
        float part = r2 * swp[lane];
        if (lane < F_IN) part += xr[lane] * sMp[lane];
        #pragma unroll
        for (int off = 16; off; off >>= 1)
            part += __shfl_xor_sync(0xffffffffu, part, off);
        if (lane == 0)
            out[n] = fmaxf(part + bias + xr[1], 0.f);
    }
}

// ---------------- launch ----------------------------------------------------
extern "C" void kernel_launch(void* const* d_in, const int* in_sizes, int n_in,
                              void* d_out, int out_size)
{
    const float* x   = (const float*)d_in[0];
    const void*  ei  = d_in[1];                 // int32 or int64, sniffed on device
    const float* We  = (const float*)d_in[2];
    const float* be  = (const float*)d_in[3];
    const float* W1  = (const float*)d_in[4];
    const float* b1  = (const float*)d_in[5];
    const float* W2  = (const float*)d_in[6];
    const float* b2  = (const float*)d_in[7];
    const float* Wp  = (const float*)d_in[8];
    const float* bp  = (const float*)d_in[9];
    float*       out = (float*)d_out;

    const int TB = 256;
    const int nodeBlocks = (N_NODES + TB - 1) / TB;       // 1 thread/node
    const int warpBlocks = (N_NODES * 32 + TB - 1) / TB;  // 1 warp/node
    const int scatBlocks = 4736;                          // 148*32 grid-stride
    const int edgeBlocks = 1184;                          // 148*8  grid-stride

    k_detect<<<1, 256>>>(ei);
    k_convert<<<edgeBlocks, TB>>>(ei);
    k_fuse_weights<<<1, 256>>>(We, be, W1, W2, Wp);
    k_cnt_init<<<nodeBlocks, TB>>>();
    k_count<<<edgeBlocks, TB>>>();
    k_dis<<<nodeBlocks, TB>>>();
    k_node1<<<warpBlocks, TB>>>(x);
    k_scatter<0><<<scatBlocks, TB>>>();
    k_node2<<<warpBlocks, TB>>>(x, b1, W2);
    k_scatter<1><<<scatBlocks, TB>>>();
    k_final<<<warpBlocks, TB>>>(x, b2, Wp, bp, out);
}

// round 6
// speedup vs baseline: 1.6920x; 1.6920x over previous
#include <cuda_runtime.h>

#define N_NODES 100000
#define N_EDGES 1600000
#define F_IN 22
#define F_HID 32
#define SCAN_BLOCKS ((N_NODES + 255) / 256)   // 391

// ---------------- scratch (static device globals; no allocation) ----------
__device__ float g_M1[F_IN * F_HID];
__device__ float g_c1[F_HID];
__device__ float g_M2b[F_IN * F_HID];
__device__ float g_c2b[F_HID];
__device__ float g_Mp[F_IN];
__device__ float g_cp;
__device__ float g_dis[N_NODES];
__device__ int   g_cnt[N_NODES];          // in-degree (edges only)
__device__ int   g_is64;
__device__ int   g_src[N_EDGES];
__device__ int   g_dst[N_EDGES];
__device__ int   g_row[N_NODES + 1];      // CSR row_ptr
__device__ int   g_cur[N_NODES];          // placement cursor
__device__ int   g_bsum[SCAN_BLOCKS];
__device__ int   g_boff[SCAN_BLOCKS];
__device__ int   g_csr[N_EDGES];          // src ids sorted by dst
__device__ __align__(16) float g_p1[(size_t)N_NODES * F_HID];
__device__ __align__(16) float g_a1[(size_t)N_NODES * F_HID];
__device__ __align__(16) float g_p2[(size_t)N_NODES * F_HID];
__device__ __align__(16) float g_a2[(size_t)N_NODES * F_HID];

// ---------------- dtype sniff: int64 vs int32 edge_index -------------------
__global__ void __launch_bounds__(256) k_detect(const void* __restrict__ ei)
{
    const long long* p64 = (const long long*)ei;
    int t = threadIdx.x;
    long long v = p64[(long long)t * (N_EDGES / 256)];
    int ok = (v >= 0 && v < N_NODES) ? 1 : 0;
    __shared__ int all_ok;
    if (t == 0) all_ok = 1;
    __syncthreads();
    if (!ok) atomicAnd(&all_ok, 0);
    __syncthreads();
    if (t == 0) g_is64 = all_ok;
}

__global__ void __launch_bounds__(256) k_zero_cnt()
{
    int i = blockIdx.x * blockDim.x + threadIdx.x;
    if (i < N_NODES) g_cnt[i] = 0;
}

// ---------------- index conversion -> int32, fused degree count ------------
__global__ void __launch_bounds__(256) k_convert(const void* __restrict__ ei)
{
    int stride = gridDim.x * blockDim.x;
    if (g_is64) {
        const long long* p = (const long long*)ei;
        for (int e = blockIdx.x * blockDim.x + threadIdx.x; e < N_EDGES; e += stride) {
            int s = (int)p[e];
            int d = (int)p[e + N_EDGES];
            g_src[e] = s;
            g_dst[e] = d;
            atomicAdd(&g_cnt[d], 1);
        }
    } else {
        const int* p = (const int*)ei;
        for (int e = blockIdx.x * blockDim.x + threadIdx.x; e < N_EDGES; e += stride) {
            int s = p[e];
            int d = p[e + N_EDGES];
            g_src[e] = s;
            g_dst[e] = d;
            atomicAdd(&g_cnt[d], 1);
        }
    }
}

__global__ void __launch_bounds__(256) k_dis()
{
    int i = blockIdx.x * blockDim.x + threadIdx.x;
    if (i < N_NODES) g_dis[i] = rsqrtf((float)(g_cnt[i] + 1));   // +1 self loop
}

// ---------------- 3-kernel exclusive scan of g_cnt -> g_row ----------------
__global__ void __launch_bounds__(256) k_scan1()
{
    __shared__ int sh[256];
    int t = threadIdx.x;
    int i = blockIdx.x * 256 + t;
    int v = (i < N_NODES) ? g_cnt[i] : 0;
    sh[t] = v;
    __syncthreads();
    #pragma unroll
    for (int off = 1; off < 256; off <<= 1) {
        int u = (t >= off) ? sh[t - off] : 0;
        __syncthreads();
        sh[t] += u;
        __syncthreads();
    }
    if (i < N_NODES) g_row[i] = sh[t] - v;        // exclusive within block
    if (t == 255) g_bsum[blockIdx.x] = sh[255];
}

__global__ void __launch_bounds__(512) k_scan2()
{
    __shared__ int sh[512];
    int t = threadIdx.x;
    int v = (t < SCAN_BLOCKS) ? g_bsum[t] : 0;
    sh[t] = v;
    __syncthreads();
    #pragma unroll
    for (int off = 1; off < 512; off <<= 1) {
        int u = (t >= off) ? sh[t - off] : 0;
        __syncthreads();
        sh[t] += u;
        __syncthreads();
    }
    if (t < SCAN_BLOCKS) g_boff[t] = sh[t] - v;   // exclusive block offsets
}

__global__ void __launch_bounds__(256) k_scan3()
{
    int i = blockIdx.x * blockDim.x + threadIdx.x;
    if (i < N_NODES) {
        int r = g_row[i] + g_boff[i >> 8];
        g_row[i] = r;
        g_cur[i] = r;
    }
    if (i == 0) g_row[N_NODES] = N_EDGES;
}

// ---------------- edge placement into CSR ----------------------------------
__global__ void __launch_bounds__(256) k_place()
{
    int stride = gridDim.x * blockDim.x;
    for (int e = blockIdx.x * blockDim.x + threadIdx.x; e < N_EDGES; e += stride) {
        int slot = atomicAdd(&g_cur[g_dst[e]], 1);
        g_csr[slot] = g_src[e];
    }
}

// ---------------- weight fusion (1 block, 256 threads) ---------------------
__global__ void __launch_bounds__(256) k_fuse_weights(
    const float* __restrict__ We, const float* __restrict__ be,
    const float* __restrict__ W1, const float* __restrict__ W2,
    const float* __restrict__ Wp)
{
    for (int t = threadIdx.x; t < F_IN * F_HID; t += 256) {
        int k = t / F_HID, j = t % F_HID;
        float m1 = 0.f, m2b = 0.f;
        for (int u = 0; u < F_HID; ++u) {
            float we = We[k * F_HID + u];
            m1  += we * W1[u * F_HID + j];
            m2b += we * W2[(F_HID + u) * F_HID + j];
        }
        g_M1[t]  = m1;
        g_M2b[t] = m2b;
    }
    int t = threadIdx.x;
    if (t < F_HID) {
        float c1 = 0.f, c2b = 0.f;
        for (int u = 0; u < F_HID; ++u) {
            c1  += be[u] * W1[u * F_HID + t];
            c2b += be[u] * W2[(F_HID + u) * F_HID + t];
        }
        g_c1[t]  = c1;
        g_c2b[t] = c2b;
    }
    if (t >= 64 && t < 64 + F_IN) {
        int k = t - 64;
        float mp = 0.f;
        for (int u = 0; u < F_HID; ++u)
            mp += We[k * F_HID + u] * Wp[F_HID + u];
        g_Mp[k] = mp;
    }
    if (t == 255) {
        float cp = 0.f;
        for (int u = 0; u < F_HID; ++u) cp += be[u] * Wp[F_HID + u];
        g_cp = cp;
    }
}

// ---------------- layer-1 node kernel: p1 = dis * (x@M1 + c1) -------------
__global__ void __launch_bounds__(256) k_node1(const float* __restrict__ x)
{
    __shared__ float sM1[F_IN * F_HID];
    __shared__ float sc1[F_HID];
    for (int i = threadIdx.x; i < F_IN * F_HID; i += blockDim.x) sM1[i] = g_M1[i];
    if (threadIdx.x < F_HID) sc1[threadIdx.x] = g_c1[threadIdx.x];
    __syncthreads();

    int lane  = threadIdx.x & 31;
    int warp  = (blockIdx.x * blockDim.x + threadIdx.x) >> 5;
    int nwarp = (gridDim.x * blockDim.x) >> 5;
    for (int n = warp; n < N_NODES; n += nwarp) {
        const float* xr = x + (size_t)n * F_IN;
        float acc = sc1[lane];
        #pragma unroll
        for (int k = 0; k < F_IN; ++k)
            acc += xr[k] * sM1[k * F_HID + lane];
        g_p1[(size_t)n * F_HID + lane] = g_dis[n] * acc;
    }
}

// ---------------- CSR gather conv: a[n] = p[n] + sum_{s in in(n)} p[s] ----
// One warp per node. 4 edges in flight (group g = lane>>3), 8 lanes x float4
// per edge -> each edge's 128B message is one coalesced line from L2.
template <int PHASE>
__global__ void __launch_bounds__(256) k_gather()
{
    const float* __restrict__ p = (PHASE == 0) ? g_p1 : g_p2;
    float* __restrict__ a       = (PHASE == 0) ? g_a1 : g_a2;

    int lane  = threadIdx.x & 31;
    int l     = lane & 7;                 // feature segment (float4)
    int g     = lane >> 3;                // edge sub-slot 0..3
    int warp  = (blockIdx.x * blockDim.x + threadIdx.x) >> 5;
    int nwarp = (gridDim.x * blockDim.x) >> 5;

    for (int n = warp; n < N_NODES; n += nwarp) {
        int beg = g_row[n];
        int end = g_row[n + 1];
        float4 acc;
        if (g == 0) {                     // self-loop seed
            acc = *reinterpret_cast<const float4*>(p + (size_t)n * F_HID + l * 4);
        } else {
            acc = make_float4(0.f, 0.f, 0.f, 0.f);
        }
        for (int e = beg + g; e < end; e += 4) {
            int s = g_csr[e];             // broadcast within 8-lane group
            float4 v = *reinterpret_cast<const float4*>(p + (size_t)s * F_HID + l * 4);
            acc.x += v.x; acc.y += v.y; acc.z += v.z; acc.w += v.w;
        }
        // reduce across the 4 edge sub-slots (lanes l, l+8, l+16, l+24)
        #pragma unroll
        for (int off = 8; off <= 16; off <<= 1) {
            acc.x += __shfl_xor_sync(0xffffffffu, acc.x, off);
            acc.y += __shfl_xor_sync(0xffffffffu, acc.y, off);
            acc.z += __shfl_xor_sync(0xffffffffu, acc.z, off);
            acc.w += __shfl_xor_sync(0xffffffffu, acc.w, off);
        }
        if (g == 0)
            *reinterpret_cast<float4*>(a + (size_t)n * F_HID + l * 4) = acc;
    }
}

// ---------------- layer-2 node kernel --------------------------------------
// r1 = relu(dis*a1 + b1); p2 = dis * (r1@W2[:32] + x@M2b + c2b)
__global__ void __launch_bounds__(256) k_node2(const float* __restrict__ x,
                                               const float* __restrict__ b1,
                                               const float* __restrict__ W2)
{
    __shared__ float sW2t[F_HID * F_HID];
    __shared__ float sM2b[F_IN * F_HID];
    __shared__ float sc2b[F_HID];
    __shared__ float sb1[F_HID];
    for (int i = threadIdx.x; i < F_HID * F_HID; i += blockDim.x) sW2t[i] = W2[i];
    for (int i = threadIdx.x; i < F_IN * F_HID; i += blockDim.x) sM2b[i] = g_M2b[i];
    if (threadIdx.x < F_HID) { sc2b[threadIdx.x] = g_c2b[threadIdx.x];
                               sb1[threadIdx.x]  = b1[threadIdx.x]; }
    __syncthreads();

    int lane  = threadIdx.x & 31;
    int warp  = (blockIdx.x * blockDim.x + threadIdx.x) >> 5;
    int nwarp = (gridDim.x * blockDim.x) >> 5;
    for (int n = warp; n < N_NODES; n += nwarp) {
        float dis = g_dis[n];
        size_t o  = (size_t)n * F_HID + lane;
        float r1  = fmaxf(dis * g_a1[o] + sb1[lane], 0.f);
        const float* xr = x + (size_t)n * F_IN;
        float acc = sc2b[lane];
        #pragma unroll
        for (int k = 0; k < F_IN; ++k)
            acc += xr[k] * sM2b[k * F_HID + lane];
        #pragma unroll
        for (int k = 0; k < F_HID; ++k) {
            float rk = __shfl_sync(0xffffffffu, r1, k);
            acc += rk * sW2t[k * F_HID + lane];
        }
        g_p2[o] = dis * acc;
    }
}

// ---------------- final kernel ---------------------------------------------
__global__ void __launch_bounds__(256) k_final(const float* __restrict__ x,
                                               const float* __restrict__ b2,
                                               const float* __restrict__ Wp,
                                               const float* __restrict__ bp,
                                               float* __restrict__ out)
{
    __shared__ float sb2[F_HID];
    __shared__ float swp[F_HID];
    __shared__ float sMp[F_IN];
    if (threadIdx.x < F_HID) { sb2[threadIdx.x] = b2[threadIdx.x];
                               swp[threadIdx.x] = Wp[threadIdx.x]; }
    if (threadIdx.x < F_IN) sMp[threadIdx.x] = g_Mp[threadIdx.x];
    __syncthreads();

    int lane  = threadIdx.x & 31;
    int warp  = (blockIdx.x * blockDim.x + threadIdx.x) >> 5;
    int nwarp = (gridDim.x * blockDim.x) >> 5;
    float bias = g_cp + bp[0];
    for (int n = warp; n < N_NODES; n += nwarp) {
        float dis = g_dis[n];
        size_t o  = (size_t)n * F_HID + lane;
        float r2  = fmaxf(dis * g_a2[o] + sb2[lane], 0.f);
        const float* xr = x + (size_t)n * F_IN;
        float part = r2 * swp[lane];
        if (lane < F_IN) part += xr[lane] * sMp[lane];
        #pragma unroll
        for (int off = 16; off; off >>= 1)
            part += __shfl_xor_sync(0xffffffffu, part, off);
        if (lane == 0)
            out[n] = fmaxf(part + bias + xr[1], 0.f);
    }
}

// ---------------- launch ----------------------------------------------------
extern "C" void kernel_launch(void* const* d_in, const int* in_sizes, int n_in,
                              void* d_out, int out_size)
{
    const float* x   = (const float*)d_in[0];
    const void*  ei  = d_in[1];
    const float* We  = (const float*)d_in[2];
    const float* be  = (const float*)d_in[3];
    const float* W1  = (const float*)d_in[4];
    const float* b1  = (const float*)d_in[5];
    const float* W2  = (const float*)d_in[6];
    const float* b2  = (const float*)d_in[7];
    const float* Wp  = (const float*)d_in[8];
    const float* bp  = (const float*)d_in[9];
    float*       out = (float*)d_out;

    const int TB = 256;
    const int nodeBlocks = (N_NODES + TB - 1) / TB;        // 391
    const int warpBlocks = (N_NODES * 32 + TB - 1) / TB;   // 12500 (1 warp/node)
    const int edgeBlocks = 1184;                           // 148*8 grid-stride

    k_detect<<<1, 256>>>(ei);
    k_zero_cnt<<<nodeBlocks, TB>>>();
    k_convert<<<edgeBlocks, TB>>>(ei);
    k_dis<<<nodeBlocks, TB>>>();
    k_fuse_weights<<<1, 256>>>(We, be, W1, W2, Wp);
    k_scan1<<<SCAN_BLOCKS, 256>>>();
    k_scan2<<<1, 512>>>();
    k_scan3<<<nodeBlocks, TB>>>();
    k_place<<<edgeBlocks, TB>>>();
    k_node1<<<warpBlocks, TB>>>(x);
    k_gather<0><<<warpBlocks, TB>>>();
    k_node2<<<warpBlocks, TB>>>(x, b1, W2);
    k_gather<1><<<warpBlocks, TB>>>();
    k_final<<<warpBlocks, TB>>>(x, b2, Wp, bp, out);
}

// round 7
// speedup vs baseline: 2.2006x; 1.3006x over previous
#include <cuda_runtime.h>

#define N_NODES 100000
#define N_EDGES 1600000
#define F_IN 22
#define F_HID 32
#define SCAN_BLOCKS ((N_NODES + 255) / 256)   // 391
#define PLACE_BLOCKS 1184                     // 148*8

// ---------------- scratch (static device globals; no allocation) ----------
__device__ float g_M1[F_IN * F_HID];
__device__ float g_c1[F_HID];
__device__ float g_M2b[F_IN * F_HID];
__device__ float g_c2b[F_HID];
__device__ float g_Mp[F_IN];
__device__ float g_cp;
__device__ float g_dis[N_NODES];
__device__ int   g_cnt[N_NODES];
__device__ int   g_is64;
__device__ int   g_src[N_EDGES];
__device__ int   g_dst[N_EDGES];
__device__ int   g_row[N_NODES + 1];
__device__ int   g_cur[N_NODES];
__device__ int   g_bsum[SCAN_BLOCKS];
__device__ int   g_boff[SCAN_BLOCKS];
__device__ int   g_csr[N_EDGES];
__device__ __align__(16) float g_p1[(size_t)N_NODES * F_HID];
__device__ __align__(16) float g_p2[(size_t)N_NODES * F_HID];

// ---------------- prep: dtype sniff (block 0) + zero degree ---------------
__global__ void __launch_bounds__(256) k_prep(const void* __restrict__ ei)
{
    int i = blockIdx.x * blockDim.x + threadIdx.x;
    if (i < N_NODES) g_cnt[i] = 0;

    if (blockIdx.x == 0) {
        const long long* p64 = (const long long*)ei;
        int t = threadIdx.x;
        long long v = p64[(long long)t * (N_EDGES / 256)];
        int ok = (v >= 0 && v < N_NODES) ? 1 : 0;
        __shared__ int all_ok;
        if (t == 0) all_ok = 1;
        __syncthreads();
        if (!ok) atomicAnd(&all_ok, 0);
        __syncthreads();
        if (t == 0) g_is64 = all_ok;
    }
}

// ---------------- index conversion -> int32, fused degree count ------------
__global__ void __launch_bounds__(256) k_convert(const void* __restrict__ ei)
{
    int stride = gridDim.x * blockDim.x;
    if (g_is64) {
        const long long* p = (const long long*)ei;
        for (int e = blockIdx.x * blockDim.x + threadIdx.x; e < N_EDGES; e += stride) {
            int s = (int)p[e];
            int d = (int)p[e + N_EDGES];
            g_src[e] = s;
            g_dst[e] = d;
            atomicAdd(&g_cnt[d], 1);
        }
    } else {
        const int* p = (const int*)ei;
        for (int e = blockIdx.x * blockDim.x + threadIdx.x; e < N_EDGES; e += stride) {
            int s = p[e];
            int d = p[e + N_EDGES];
            g_src[e] = s;
            g_dst[e] = d;
            atomicAdd(&g_cnt[d], 1);
        }
    }
}

// ---------------- scan stage 1 (+ deg^{-1/2}) -------------------------------
__global__ void __launch_bounds__(256) k_scan1()
{
    __shared__ int sh[256];
    int t = threadIdx.x;
    int i = blockIdx.x * 256 + t;
    int v = (i < N_NODES) ? g_cnt[i] : 0;
    if (i < N_NODES) g_dis[i] = rsqrtf((float)(v + 1));   // +1 self loop
    sh[t] = v;
    __syncthreads();
    #pragma unroll
    for (int off = 1; off < 256; off <<= 1) {
        int u = (t >= off) ? sh[t - off] : 0;
        __syncthreads();
        sh[t] += u;
        __syncthreads();
    }
    if (i < N_NODES) g_row[i] = sh[t] - v;
    if (t == 255) g_bsum[blockIdx.x] = sh[255];
}

// ---------------- scan stage 2 (block 0) + weight fusion (block 1) ---------
__global__ void __launch_bounds__(512) k_scan2w(
    const float* __restrict__ We, const float* __restrict__ be,
    const float* __restrict__ W1, const float* __restrict__ W2,
    const float* __restrict__ Wp)
{
    int t = threadIdx.x;
    if (blockIdx.x == 0) {
        __shared__ int sh[512];
        int v = (t < SCAN_BLOCKS) ? g_bsum[t] : 0;
        sh[t] = v;
        __syncthreads();
        #pragma unroll
        for (int off = 1; off < 512; off <<= 1) {
            int u = (t >= off) ? sh[t - off] : 0;
            __syncthreads();
            sh[t] += u;
            __syncthreads();
        }
        if (t < SCAN_BLOCKS) g_boff[t] = sh[t] - v;
    } else {
        for (int q = t; q < F_IN * F_HID; q += 512) {
            int k = q / F_HID, j = q % F_HID;
            float m1 = 0.f, m2b = 0.f;
            for (int u = 0; u < F_HID; ++u) {
                float we = We[k * F_HID + u];
                m1  += we * W1[u * F_HID + j];
                m2b += we * W2[(F_HID + u) * F_HID + j];
            }
            g_M1[q]  = m1;
            g_M2b[q] = m2b;
        }
        if (t < F_HID) {
            float c1 = 0.f, c2b = 0.f;
            for (int u = 0; u < F_HID; ++u) {
                c1  += be[u] * W1[u * F_HID + t];
                c2b += be[u] * W2[(F_HID + u) * F_HID + t];
            }
            g_c1[t]  = c1;
            g_c2b[t] = c2b;
        }
        if (t >= 64 && t < 64 + F_IN) {
            int k = t - 64;
            float mp = 0.f;
            for (int u = 0; u < F_HID; ++u)
                mp += We[k * F_HID + u] * Wp[F_HID + u];
            g_Mp[k] = mp;
        }
        if (t == 511) {
            float cp = 0.f;
            for (int u = 0; u < F_HID; ++u) cp += be[u] * Wp[F_HID + u];
            g_cp = cp;
        }
    }
}

// ---------------- scan stage 3 ----------------------------------------------
__global__ void __launch_bounds__(256) k_scan3()
{
    int i = blockIdx.x * blockDim.x + threadIdx.x;
    if (i < N_NODES) {
        int r = g_row[i] + g_boff[i >> 8];
        g_row[i] = r;
        g_cur[i] = r;
    }
    if (i == 0) g_row[N_NODES] = N_EDGES;
}

// ---------------- fused: CSR edge placement + layer-1 node kernel ----------
// Blocks [0, PLACE_BLOCKS) place edges; remaining blocks compute
// p1 = dis * (x@M1 + c1), one warp per node (grid-stride).
__global__ void __launch_bounds__(256) k_place_node1(const float* __restrict__ x)
{
    if (blockIdx.x < PLACE_BLOCKS) {
        int stride = PLACE_BLOCKS * 256;
        for (int e = blockIdx.x * 256 + threadIdx.x; e < N_EDGES; e += stride) {
            int slot = atomicAdd(&g_cur[g_dst[e]], 1);
            g_csr[slot] = g_src[e];
        }
        return;
    }

    __shared__ float sM1[F_IN * F_HID];
    __shared__ float sc1[F_HID];
    for (int i = threadIdx.x; i < F_IN * F_HID; i += 256) sM1[i] = g_M1[i];
    if (threadIdx.x < F_HID) sc1[threadIdx.x] = g_c1[threadIdx.x];
    __syncthreads();

    int lane  = threadIdx.x & 31;
    int warp  = ((blockIdx.x - PLACE_BLOCKS) * 256 + threadIdx.x) >> 5;
    int nwarp = ((gridDim.x - PLACE_BLOCKS) * 256) >> 5;
    for (int n = warp; n < N_NODES; n += nwarp) {
        const float* xr = x + (size_t)n * F_IN;
        float acc = sc1[lane];
        #pragma unroll
        for (int k = 0; k < F_IN; ++k)
            acc += xr[k] * sM1[k * F_HID + lane];
        g_p1[(size_t)n * F_HID + lane] = g_dis[n] * acc;
    }
}

// Redistribute: after xor-reduce every lane holds the float4 sum of its
// segment (lane&7). Lane j needs feature j = segment j>>2, component j&3.
__device__ __forceinline__ float redist32(float4 acc, int lane)
{
    int srcl = lane >> 2;
    float fx = __shfl_sync(0xffffffffu, acc.x, srcl);
    float fy = __shfl_sync(0xffffffffu, acc.y, srcl);
    float fz = __shfl_sync(0xffffffffu, acc.z, srcl);
    float fw = __shfl_sync(0xffffffffu, acc.w, srcl);
    int c = lane & 3;
    return (c == 0) ? fx : (c == 1) ? fy : (c == 2) ? fz : fw;
}

// Gather core: returns per-lane feature of a[n] = p[n] + sum_{s in in(n)} p[s]
__device__ __forceinline__ float gather_node(const float* __restrict__ p, int n,
                                             int lane, int l, int g)
{
    int beg = g_row[n];
    int end = g_row[n + 1];
    float4 acc;
    if (g == 0) {
        acc = *reinterpret_cast<const float4*>(p + (size_t)n * F_HID + l * 4);
    } else {
        acc = make_float4(0.f, 0.f, 0.f, 0.f);
    }
    int e = beg + g;
    for (; e + 4 < end; e += 8) {                 // 2 edges in flight per group
        int s0 = g_csr[e];
        int s1 = g_csr[e + 4];
        float4 v0 = *reinterpret_cast<const float4*>(p + (size_t)s0 * F_HID + l * 4);
        float4 v1 = *reinterpret_cast<const float4*>(p + (size_t)s1 * F_HID + l * 4);
        acc.x += v0.x + v1.x; acc.y += v0.y + v1.y;
        acc.z += v0.z + v1.z; acc.w += v0.w + v1.w;
    }
    if (e < end) {
        int s = g_csr[e];
        float4 v = *reinterpret_cast<const float4*>(p + (size_t)s * F_HID + l * 4);
        acc.x += v.x; acc.y += v.y; acc.z += v.z; acc.w += v.w;
    }
    #pragma unroll
    for (int off = 8; off <= 16; off <<= 1) {
        acc.x += __shfl_xor_sync(0xffffffffu, acc.x, off);
        acc.y += __shfl_xor_sync(0xffffffffu, acc.y, off);
        acc.z += __shfl_xor_sync(0xffffffffu, acc.z, off);
        acc.w += __shfl_xor_sync(0xffffffffu, acc.w, off);
    }
    return redist32(acc, lane);
}

// ---------------- fused gather1 + node2 -------------------------------------
// a1 = gather(p1); r1 = relu(dis*a1 + b1); p2 = dis*(r1@W2[:32] + x@M2b + c2b)
__global__ void __launch_bounds__(256) k_gather_node2(const float* __restrict__ x,
                                                      const float* __restrict__ b1,
                                                      const float* __restrict__ W2)
{
    __shared__ float sW2t[F_HID * F_HID];
    __shared__ float sM2b[F_IN * F_HID];
    __shared__ float sc2b[F_HID];
    __shared__ float sb1[F_HID];
    for (int i = threadIdx.x; i < F_HID * F_HID; i += 256) sW2t[i] = W2[i];
    for (int i = threadIdx.x; i < F_IN * F_HID; i += 256) sM2b[i] = g_M2b[i];
    if (threadIdx.x < F_HID) { sc2b[threadIdx.x] = g_c2b[threadIdx.x];
                               sb1[threadIdx.x]  = b1[threadIdx.x]; }
    __syncthreads();

    int lane  = threadIdx.x & 31;
    int l     = lane & 7;
    int g     = lane >> 3;
    int warp  = (blockIdx.x * 256 + threadIdx.x) >> 5;
    int nwarp = (gridDim.x * 256) >> 5;

    for (int n = warp; n < N_NODES; n += nwarp) {
        float a1j = gather_node(g_p1, n, lane, l, g);
        float dis = g_dis[n];
        float r1  = fmaxf(dis * a1j + sb1[lane], 0.f);

        const float* xr = x + (size_t)n * F_IN;
        float acc = sc2b[lane];
        #pragma unroll
        for (int k = 0; k < F_IN; ++k)
            acc += xr[k] * sM2b[k * F_HID + lane];
        #pragma unroll
        for (int k = 0; k < F_HID; ++k) {
            float rk = __shfl_sync(0xffffffffu, r1, k);
            acc += rk * sW2t[k * F_HID + lane];
        }
        g_p2[(size_t)n * F_HID + lane] = dis * acc;
    }
}

// ---------------- fused gather2 + prediction --------------------------------
// a2 = gather(p2); r2 = relu(dis*a2 + b2);
// out = relu(r2@Wp[:32] + x@Mp + cp + bp + x[:,1])
__global__ void __launch_bounds__(256) k_gather_final(const float* __restrict__ x,
                                                      const float* __restrict__ b2,
                                                      const float* __restrict__ Wp,
                                                      const float* __restrict__ bp,
                                                      float* __restrict__ out)
{
    __shared__ float sb2[F_HID];
    __shared__ float swp[F_HID];
    __shared__ float sMp[F_IN];
    if (threadIdx.x < F_HID) { sb2[threadIdx.x] = b2[threadIdx.x];
                               swp[threadIdx.x] = Wp[threadIdx.x]; }
    if (threadIdx.x < F_IN) sMp[threadIdx.x] = g_Mp[threadIdx.x];
    __syncthreads();

    int lane  = threadIdx.x & 31;
    int l     = lane & 7;
    int g     = lane >> 3;
    int warp  = (blockIdx.x * 256 + threadIdx.x) >> 5;
    int nwarp = (gridDim.x * 256) >> 5;
    float bias = g_cp + bp[0];

    for (int n = warp; n < N_NODES; n += nwarp) {
        float a2j = gather_node(g_p2, n, lane, l, g);
        float dis = g_dis[n];
        float r2  = fmaxf(dis * a2j + sb2[lane], 0.f);

        const float* xr = x + (size_t)n * F_IN;
        float part = r2 * swp[lane];
        if (lane < F_IN) part += xr[lane] * sMp[lane];
        #pragma unroll
        for (int off = 16; off; off >>= 1)
            part += __shfl_xor_sync(0xffffffffu, part, off);
        if (lane == 0)
            out[n] = fmaxf(part + bias + xr[1], 0.f);
    }
}

// ---------------- launch ----------------------------------------------------
extern "C" void kernel_launch(void* const* d_in, const int* in_sizes, int n_in,
                              void* d_out, int out_size)
{
    const float* x   = (const float*)d_in[0];
    const void*  ei  = d_in[1];
    const float* We  = (const float*)d_in[2];
    const float* be  = (const float*)d_in[3];
    const float* W1  = (const float*)d_in[4];
    const float* b1  = (const float*)d_in[5];
    const float* W2  = (const float*)d_in[6];
    const float* b2  = (const float*)d_in[7];
    const float* Wp  = (const float*)d_in[8];
    const float* bp  = (const float*)d_in[9];
    float*       out = (float*)d_out;

    const int TB = 256;
    const int nodeBlocks   = (N_NODES + TB - 1) / TB;   // 391
    const int node1Blocks  = 2368;                      // warp/node grid-stride
    const int gatherBlocks = 2960;                      // warp/node grid-stride

    k_prep<<<nodeBlocks, TB>>>(ei);
    k_convert<<<PLACE_BLOCKS, TB>>>(ei);
    k_scan1<<<SCAN_BLOCKS, 256>>>();
    k_scan2w<<<2, 512>>>(We, be, W1, W2, Wp);
    k_scan3<<<nodeBlocks, TB>>>();
    k_place_node1<<<PLACE_BLOCKS + node1Blocks, TB>>>(x);
    k_gather_node2<<<gatherBlocks, TB>>>(x, b1, W2);
    k_gather_final<<<gatherBlocks, TB>>>(x, b2, Wp, bp, out);
}

// round 8
// speedup vs baseline: 2.2314x; 1.0140x over previous
#include <cuda_runtime.h>

#define N_NODES 100000
#define N_EDGES 1600000
#define F_IN 22
#define F_HID 32
#define SCAN_BLOCKS ((N_NODES + 255) / 256)   // 391
#define PLACE_BLOCKS 1184                     // 148*8

// ---------------- scratch (static device globals; no allocation) ----------
__device__ float g_M1[F_IN * F_HID];
__device__ float g_c1[F_HID];
__device__ float g_M2b[F_IN * F_HID];
__device__ float g_c2b[F_HID];
__device__ float g_Mp[F_IN];
__device__ float g_cp;
__device__ float g_dis[N_NODES];
__device__ int   g_cnt[N_NODES];
__device__ int   g_is64;
__device__ int   g_row[N_NODES + 1];
__device__ int   g_cur[N_NODES];
__device__ int   g_bsum[SCAN_BLOCKS];
__device__ int   g_boff[SCAN_BLOCKS];
__device__ int   g_csr[N_EDGES];
__device__ __align__(16) float g_p1[(size_t)N_NODES * F_HID];
__device__ __align__(16) float g_p2[(size_t)N_NODES * F_HID];

// ---------------- prep: zero degree + dtype sniff + weight fusion ---------
// Blocks [0, SCAN_BLOCKS): zero g_cnt (block 0 also sniffs dtype).
// Block SCAN_BLOCKS: weight fusion (independent of everything else).
__global__ void __launch_bounds__(256) k_prep(
    const void* __restrict__ ei,
    const float* __restrict__ We, const float* __restrict__ be,
    const float* __restrict__ W1, const float* __restrict__ W2,
    const float* __restrict__ Wp)
{
    int t = threadIdx.x;
    if (blockIdx.x < SCAN_BLOCKS) {
        int i = blockIdx.x * 256 + t;
        if (i < N_NODES) g_cnt[i] = 0;
        if (blockIdx.x == 0) {
            const long long* p64 = (const long long*)ei;
            long long v = p64[(long long)t * (N_EDGES / 256)];
            int ok = (v >= 0 && v < N_NODES) ? 1 : 0;
            __shared__ int all_ok;
            if (t == 0) all_ok = 1;
            __syncthreads();
            if (!ok) atomicAnd(&all_ok, 0);
            __syncthreads();
            if (t == 0) g_is64 = all_ok;
        }
        return;
    }
    // weight fusion block
    for (int q = t; q < F_IN * F_HID; q += 256) {
        int k = q / F_HID, j = q % F_HID;
        float m1 = 0.f, m2b = 0.f;
        for (int u = 0; u < F_HID; ++u) {
            float we = We[k * F_HID + u];
            m1  += we * W1[u * F_HID + j];
            m2b += we * W2[(F_HID + u) * F_HID + j];
        }
        g_M1[q]  = m1;
        g_M2b[q] = m2b;
    }
    if (t < F_HID) {
        float c1 = 0.f, c2b = 0.f;
        for (int u = 0; u < F_HID; ++u) {
            c1  += be[u] * W1[u * F_HID + t];
            c2b += be[u] * W2[(F_HID + u) * F_HID + t];
        }
        g_c1[t]  = c1;
        g_c2b[t] = c2b;
    }
    if (t >= 64 && t < 64 + F_IN) {
        int k = t - 64;
        float mp = 0.f;
        for (int u = 0; u < F_HID; ++u)
            mp += We[k * F_HID + u] * Wp[F_HID + u];
        g_Mp[k] = mp;
    }
    if (t == 255) {
        float cp = 0.f;
        for (int u = 0; u < F_HID; ++u) cp += be[u] * Wp[F_HID + u];
        g_cp = cp;
    }
}

// ---------------- degree count (reads dst half of edge_index only) ---------
__global__ void __launch_bounds__(256) k_count(const void* __restrict__ ei)
{
    int stride = gridDim.x * blockDim.x;
    if (g_is64) {
        const long long* p = (const long long*)ei + N_EDGES;
        for (int e = blockIdx.x * blockDim.x + threadIdx.x; e < N_EDGES; e += stride)
            atomicAdd(&g_cnt[(int)p[e]], 1);
    } else {
        const int* p = (const int*)ei + N_EDGES;
        for (int e = blockIdx.x * blockDim.x + threadIdx.x; e < N_EDGES; e += stride)
            atomicAdd(&g_cnt[p[e]], 1);
    }
}

// ---------------- scan stage 1 (warp-shuffle block scan, + deg^{-1/2}) -----
__global__ void __launch_bounds__(256) k_scan1()
{
    __shared__ int wsum[8];
    int t = threadIdx.x;
    int lane = t & 31, w = t >> 5;
    int i = blockIdx.x * 256 + t;
    int v = (i < N_NODES) ? g_cnt[i] : 0;
    if (i < N_NODES) g_dis[i] = rsqrtf((float)(v + 1));   // +1 self loop

    int s = v;                                            // inclusive warp scan
    #pragma unroll
    for (int off = 1; off < 32; off <<= 1) {
        int u = __shfl_up_sync(0xffffffffu, s, off);
        if (lane >= off) s += u;
    }
    if (lane == 31) wsum[w] = s;
    __syncthreads();
    if (w == 0) {
        int ws = (lane < 8) ? wsum[lane] : 0;
        #pragma unroll
        for (int off = 1; off < 8; off <<= 1) {
            int u = __shfl_up_sync(0xffffffffu, ws, off);
            if (lane >= off) ws += u;
        }
        if (lane < 8) wsum[lane] = ws;
    }
    __syncthreads();
    int base = (w > 0) ? wsum[w - 1] : 0;
    if (i < N_NODES) g_row[i] = base + s - v;             // exclusive
    if (t == 255) g_bsum[blockIdx.x] = base + s;
}

// ---------------- scan stage 2 (1 block, warp-shuffle two-level) -----------
__global__ void __launch_bounds__(512) k_scan2()
{
    __shared__ int wsum[16];
    int t = threadIdx.x;
    int lane = t & 31, w = t >> 5;
    int v = (t < SCAN_BLOCKS) ? g_bsum[t] : 0;

    int s = v;
    #pragma unroll
    for (int off = 1; off < 32; off <<= 1) {
        int u = __shfl_up_sync(0xffffffffu, s, off);
        if (lane >= off) s += u;
    }
    if (lane == 31) wsum[w] = s;
    __syncthreads();
    if (w == 0) {
        int ws = (lane < 16) ? wsum[lane] : 0;
        #pragma unroll
        for (int off = 1; off < 16; off <<= 1) {
            int u = __shfl_up_sync(0xffffffffu, ws, off);
            if (lane >= off) ws += u;
        }
        if (lane < 16) wsum[lane] = ws;
    }
    __syncthreads();
    int base = (w > 0) ? wsum[w - 1] : 0;
    if (t < SCAN_BLOCKS) g_boff[t] = base + s - v;        // exclusive
}

// ---------------- scan stage 3 ----------------------------------------------
__global__ void __launch_bounds__(256) k_scan3()
{
    int i = blockIdx.x * blockDim.x + threadIdx.x;
    if (i < N_NODES) {
        int r = g_row[i] + g_boff[i >> 8];
        g_row[i] = r;
        g_cur[i] = r;
    }
    if (i == 0) g_row[N_NODES] = N_EDGES;
}

// ---------------- fused: CSR edge placement + layer-1 node kernel ----------
__global__ void __launch_bounds__(256) k_place_node1(const void* __restrict__ ei,
                                                     const float* __restrict__ x)
{
    if (blockIdx.x < PLACE_BLOCKS) {
        int stride = PLACE_BLOCKS * 256;
        if (g_is64) {
            const long long* ps = (const long long*)ei;
            const long long* pd = ps + N_EDGES;
            for (int e = blockIdx.x * 256 + threadIdx.x; e < N_EDGES; e += stride) {
                int slot = atomicAdd(&g_cur[(int)pd[e]], 1);
                g_csr[slot] = (int)ps[e];
            }
        } else {
            const int* ps = (const int*)ei;
            const int* pd = ps + N_EDGES;
            for (int e = blockIdx.x * 256 + threadIdx.x; e < N_EDGES; e += stride) {
                int slot = atomicAdd(&g_cur[pd[e]], 1);
                g_csr[slot] = ps[e];
            }
        }
        return;
    }

    __shared__ float sM1[F_IN * F_HID];
    __shared__ float sc1[F_HID];
    for (int i = threadIdx.x; i < F_IN * F_HID; i += 256) sM1[i] = g_M1[i];
    if (threadIdx.x < F_HID) sc1[threadIdx.x] = g_c1[threadIdx.x];
    __syncthreads();

    int lane  = threadIdx.x & 31;
    int warp  = ((blockIdx.x - PLACE_BLOCKS) * 256 + threadIdx.x) >> 5;
    int nwarp = ((gridDim.x - PLACE_BLOCKS) * 256) >> 5;
    for (int n = warp; n < N_NODES; n += nwarp) {
        const float* xr = x + (size_t)n * F_IN;
        float acc = sc1[lane];
        #pragma unroll
        for (int k = 0; k < F_IN; ++k)
            acc += xr[k] * sM1[k * F_HID + lane];
        g_p1[(size_t)n * F_HID + lane] = g_dis[n] * acc;
    }
}

// Redistribute: after xor-reduce every lane holds the float4 sum of its
// segment (lane&7). Lane j needs feature j = segment j>>2, component j&3.
__device__ __forceinline__ float redist32(float4 acc, int lane)
{
    int srcl = lane >> 2;
    float fx = __shfl_sync(0xffffffffu, acc.x, srcl);
    float fy = __shfl_sync(0xffffffffu, acc.y, srcl);
    float fz = __shfl_sync(0xffffffffu, acc.z, srcl);
    float fw = __shfl_sync(0xffffffffu, acc.w, srcl);
    int c = lane & 3;
    return (c == 0) ? fx : (c == 1) ? fy : (c == 2) ? fz : fw;
}

// Gather core: per-lane feature of a[n] = p[n] + sum_{s in in(n)} p[s].
// 4 edges in flight per 8-lane group (16 edges/warp/iter).
__device__ __forceinline__ float gather_node(const float* __restrict__ p, int n,
                                             int lane, int l, int g)
{
    int beg = g_row[n];
    int end = g_row[n + 1];
    float4 acc;
    if (g == 0) {
        acc = *reinterpret_cast<const float4*>(p + (size_t)n * F_HID + l * 4);
    } else {
        acc = make_float4(0.f, 0.f, 0.f, 0.f);
    }
    int e = beg + g;
    for (; e + 12 < end; e += 16) {
        int s0 = g_csr[e];
        int s1 = g_csr[e + 4];
        int s2 = g_csr[e + 8];
        int s3 = g_csr[e + 12];
        float4 v0 = *reinterpret_cast<const float4*>(p + (size_t)s0 * F_HID + l * 4);
        float4 v1 = *reinterpret_cast<const float4*>(p + (size_t)s1 * F_HID + l * 4);
        float4 v2 = *reinterpret_cast<const float4*>(p + (size_t)s2 * F_HID + l * 4);
        float4 v3 = *reinterpret_cast<const float4*>(p + (size_t)s3 * F_HID + l * 4);
        acc.x += (v0.x + v1.x) + (v2.x + v3.x);
        acc.y += (v0.y + v1.y) + (v2.y + v3.y);
        acc.z += (v0.z + v1.z) + (v2.z + v3.z);
        acc.w += (v0.w + v1.w) + (v2.w + v3.w);
    }
    for (; e < end; e += 4) {
        int s = g_csr[e];
        float4 v = *reinterpret_cast<const float4*>(p + (size_t)s * F_HID + l * 4);
        acc.x += v.x; acc.y += v.y; acc.z += v.z; acc.w += v.w;
    }
    #pragma unroll
    for (int off = 8; off <= 16; off <<= 1) {
        acc.x += __shfl_xor_sync(0xffffffffu, acc.x, off);
        acc.y += __shfl_xor_sync(0xffffffffu, acc.y, off);
        acc.z += __shfl_xor_sync(0xffffffffu, acc.z, off);
        acc.w += __shfl_xor_sync(0xffffffffu, acc.w, off);
    }
    return redist32(acc, lane);
}

// ---------------- fused gather1 + node2 -------------------------------------
__global__ void __launch_bounds__(256) k_gather_node2(const float* __restrict__ x,
                                                      const float* __restrict__ b1,
                                                      const float* __restrict__ W2)
{
    __shared__ float sW2t[F_HID * F_HID];
    __shared__ float sM2b[F_IN * F_HID];
    __shared__ float sc2b[F_HID];
    __shared__ float sb1[F_HID];
    for (int i = threadIdx.x; i < F_HID * F_HID; i += 256) sW2t[i] = W2[i];
    for (int i = threadIdx.x; i < F_IN * F_HID; i += 256) sM2b[i] = g_M2b[i];
    if (threadIdx.x < F_HID) { sc2b[threadIdx.x] = g_c2b[threadIdx.x];
                               sb1[threadIdx.x]  = b1[threadIdx.x]; }
    __syncthreads();

    int lane  = threadIdx.x & 31;
    int l     = lane & 7;
    int g     = lane >> 3;
    int warp  = (blockIdx.x * 256 + threadIdx.x) >> 5;
    int nwarp = (gridDim.x * 256) >> 5;

    for (int n = warp; n < N_NODES; n += nwarp) {
        float a1j = gather_node(g_p1, n, lane, l, g);
        float dis = g_dis[n];
        float r1  = fmaxf(dis * a1j + sb1[lane], 0.f);

        const float* xr = x + (size_t)n * F_IN;
        float acc = sc2b[lane];
        #pragma unroll
        for (int k = 0; k < F_IN; ++k)
            acc += xr[k] * sM2b[k * F_HID + lane];
        #pragma unroll
        for (int k = 0; k < F_HID; ++k) {
            float rk = __shfl_sync(0xffffffffu, r1, k);
            acc += rk * sW2t[k * F_HID + lane];
        }
        g_p2[(size_t)n * F_HID + lane] = dis * acc;
    }
}

// ---------------- fused gather2 + prediction --------------------------------
__global__ void __launch_bounds__(256) k_gather_final(const float* __restrict__ x,
                                                      const float* __restrict__ b2,
                                                      const float* __restrict__ Wp,
                                                      const float* __restrict__ bp,
                                                      float* __restrict__ out)
{
    __shared__ float sb2[F_HID];
    __shared__ float swp[F_HID];
    __shared__ float sMp[F_IN];
    if (threadIdx.x < F_HID) { sb2[threadIdx.x] = b2[threadIdx.x];
                               swp[threadIdx.x] = Wp[threadIdx.x]; }
    if (threadIdx.x < F_IN) sMp[threadIdx.x] = g_Mp[threadIdx.x];
    __syncthreads();

    int lane  = threadIdx.x & 31;
    int l     = lane & 7;
    int g     = lane >> 3;
    int warp  = (blockIdx.x * 256 + threadIdx.x) >> 5;
    int nwarp = (gridDim.x * 256) >> 5;
    float bias = g_cp + bp[0];

    for (int n = warp; n < N_NODES; n += nwarp) {
        float a2j = gather_node(g_p2, n, lane, l, g);
        float dis = g_dis[n];
        float r2  = fmaxf(dis * a2j + sb2[lane], 0.f);

        const float* xr = x + (size_t)n * F_IN;
        float part = r2 * swp[lane];
        if (lane < F_IN) part += xr[lane] * sMp[lane];
        #pragma unroll
        for (int off = 16; off; off >>= 1)
            part += __shfl_xor_sync(0xffffffffu, part, off);
        if (lane == 0)
            out[n] = fmaxf(part + bias + xr[1], 0.f);
    }
}

// ---------------- launch ----------------------------------------------------
extern "C" void kernel_launch(void* const* d_in, const int* in_sizes, int n_in,
                              void* d_out, int out_size)
{
    const float* x   = (const float*)d_in[0];
    const void*  ei  = d_in[1];
    const float* We  = (const float*)d_in[2];
    const float* be  = (const float*)d_in[3];
    const float* W1  = (const float*)d_in[4];
    const float* b1  = (const float*)d_in[5];
    const float* W2  = (const float*)d_in[6];
    const float* b2  = (const float*)d_in[7];
    const float* Wp  = (const float*)d_in[8];
    const float* bp  = (const float*)d_in[9];
    float*       out = (float*)d_out;

    const int TB = 256;
    const int nodeBlocks   = SCAN_BLOCKS;               // 391
    const int node1Blocks  = 2368;
    const int gatherBlocks = 2960;

    k_prep<<<SCAN_BLOCKS + 1, TB>>>(ei, We, be, W1, W2, Wp);
    k_count<<<PLACE_BLOCKS, TB>>>(ei);
    k_scan1<<<SCAN_BLOCKS, TB>>>();
    k_scan2<<<1, 512>>>();
    k_scan3<<<nodeBlocks, TB>>>();
    k_place_node1<<<PLACE_BLOCKS + node1Blocks, TB>>>(ei, x);
    k_gather_node2<<<gatherBlocks, TB>>>(x, b1, W2);
    k_gather_final<<<gatherBlocks, TB>>>(x, b2, Wp, bp, out);
}

// round 9
// speedup vs baseline: 2.3683x; 1.0614x over previous
#include <cuda_runtime.h>

#define N_NODES 100000
#define N_EDGES 1600000
#define F_IN 22
#define F_HID 32
#define CAP 96                                // bucket capacity per node
#define ZERO_BLOCKS ((N_NODES + 255) / 256)   // 391
#define PLACE_BLOCKS 1184                     // 148*8
#define MAX_SPILL 4096

// ---------------- scratch (static device globals; no allocation) ----------
__device__ float g_M1[F_IN * F_HID];
__device__ float g_c1[F_HID];
__device__ float g_M2b[F_IN * F_HID];
__device__ float g_c2b[F_HID];
__device__ float g_Mp[F_IN];
__device__ float g_cp;
__device__ float g_dis[N_NODES];
__device__ int   g_slot[N_NODES];            // in-degree counter / bucket fill
__device__ int   g_is64;
__device__ int   g_spill_n;
__device__ int2  g_spill[MAX_SPILL];         // (dst, src) overflow edges
__device__ int   g_csr[(size_t)N_NODES * CAP];
__device__ __align__(16) float g_p1[(size_t)N_NODES * F_HID];
__device__ __align__(16) float g_p2[(size_t)N_NODES * F_HID];

// ---------------- prep: zero buckets + dtype sniff + weight fusion --------
// Blocks [0, ZERO_BLOCKS): zero g_slot (block 0 also sniffs dtype + spill ctr).
// Block ZERO_BLOCKS: weight fusion (independent of everything else).
__global__ void __launch_bounds__(256) k_prep(
    const void* __restrict__ ei,
    const float* __restrict__ We, const float* __restrict__ be,
    const float* __restrict__ W1, const float* __restrict__ W2,
    const float* __restrict__ Wp)
{
    int t = threadIdx.x;
    if (blockIdx.x < ZERO_BLOCKS) {
        int i = blockIdx.x * 256 + t;
        if (i < N_NODES) g_slot[i] = 0;
        if (blockIdx.x == 0) {
            const long long* p64 = (const long long*)ei;
            long long v = p64[(long long)t * (N_EDGES / 256)];
            int ok = (v >= 0 && v < N_NODES) ? 1 : 0;
            __shared__ int all_ok;
            if (t == 0) { all_ok = 1; g_spill_n = 0; }
            __syncthreads();
            if (!ok) atomicAnd(&all_ok, 0);
            __syncthreads();
            if (t == 0) g_is64 = all_ok;
        }
        return;
    }
    // weight fusion block
    for (int q = t; q < F_IN * F_HID; q += 256) {
        int k = q / F_HID, j = q % F_HID;
        float m1 = 0.f, m2b = 0.f;
        for (int u = 0; u < F_HID; ++u) {
            float we = We[k * F_HID + u];
            m1  += we * W1[u * F_HID + j];
            m2b += we * W2[(F_HID + u) * F_HID + j];
        }
        g_M1[q]  = m1;
        g_M2b[q] = m2b;
    }
    if (t < F_HID) {
        float c1 = 0.f, c2b = 0.f;
        for (int u = 0; u < F_HID; ++u) {
            c1  += be[u] * W1[u * F_HID + t];
            c2b += be[u] * W2[(F_HID + u) * F_HID + t];
        }
        g_c1[t]  = c1;
        g_c2b[t] = c2b;
    }
    if (t >= 64 && t < 64 + F_IN) {
        int k = t - 64;
        float mp = 0.f;
        for (int u = 0; u < F_HID; ++u)
            mp += We[k * F_HID + u] * Wp[F_HID + u];
        g_Mp[k] = mp;
    }
    if (t == 255) {
        float cp = 0.f;
        for (int u = 0; u < F_HID; ++u) cp += be[u] * Wp[F_HID + u];
        g_cp = cp;
    }
}

// ---------------- bucket placement (single pass over edge_index) -----------
__device__ __forceinline__ void place_edge(int s, int d)
{
    int slot = atomicAdd(&g_slot[d], 1);
    if (slot < CAP) {
        g_csr[(size_t)d * CAP + slot] = s;
    } else {
        int sp = atomicAdd(&g_spill_n, 1);
        if (sp < MAX_SPILL) g_spill[sp] = make_int2(d, s);
    }
}

__global__ void __launch_bounds__(256) k_place(const void* __restrict__ ei)
{
    int stride = gridDim.x * blockDim.x;
    if (g_is64) {
        const long long* ps = (const long long*)ei;
        const long long* pd = ps + N_EDGES;
        for (int e = blockIdx.x * blockDim.x + threadIdx.x; e < N_EDGES; e += stride)
            place_edge((int)ps[e], (int)pd[e]);
    } else {
        const int* ps = (const int*)ei;
        const int* pd = ps + N_EDGES;
        for (int e = blockIdx.x * blockDim.x + threadIdx.x; e < N_EDGES; e += stride)
            place_edge(ps[e], pd[e]);
    }
}

// ---------------- layer-1 node kernel: dis + p1 = dis*(x@M1 + c1) ----------
__global__ void __launch_bounds__(256) k_node1(const float* __restrict__ x)
{
    __shared__ float sM1[F_IN * F_HID];
    __shared__ float sc1[F_HID];
    for (int i = threadIdx.x; i < F_IN * F_HID; i += 256) sM1[i] = g_M1[i];
    if (threadIdx.x < F_HID) sc1[threadIdx.x] = g_c1[threadIdx.x];
    __syncthreads();

    int lane  = threadIdx.x & 31;
    int warp  = (blockIdx.x * 256 + threadIdx.x) >> 5;
    int nwarp = (gridDim.x * 256) >> 5;
    for (int n = warp; n < N_NODES; n += nwarp) {
        float dis = rsqrtf((float)(g_slot[n] + 1));       // +1 self loop
        if (lane == 0) g_dis[n] = dis;
        const float* xr = x + (size_t)n * F_IN;
        float acc = sc1[lane];
        #pragma unroll
        for (int k = 0; k < F_IN; ++k)
            acc += xr[k] * sM1[k * F_HID + lane];
        g_p1[(size_t)n * F_HID + lane] = dis * acc;
    }
}

// Redistribute: after xor-reduce every lane holds the float4 sum of its
// segment (lane&7). Lane j needs feature j = segment j>>2, component j&3.
__device__ __forceinline__ float redist32(float4 acc, int lane)
{
    int srcl = lane >> 2;
    float fx = __shfl_sync(0xffffffffu, acc.x, srcl);
    float fy = __shfl_sync(0xffffffffu, acc.y, srcl);
    float fz = __shfl_sync(0xffffffffu, acc.z, srcl);
    float fw = __shfl_sync(0xffffffffu, acc.w, srcl);
    int c = lane & 3;
    return (c == 0) ? fx : (c == 1) ? fy : (c == 2) ? fz : fw;
}

// Gather core: per-lane feature of a[n] = p[n] + sum_{s in in(n)} p[s].
// 4 edges in flight per 8-lane group; bucket row g_csr[n*CAP ..].
__device__ __forceinline__ float gather_node(const float* __restrict__ p, int n,
                                             int lane, int l, int g)
{
    int cnt = min(g_slot[n], CAP);
    const int* row = g_csr + (size_t)n * CAP;
    float4 acc;
    if (g == 0) {
        acc = *reinterpret_cast<const float4*>(p + (size_t)n * F_HID + l * 4);
    } else {
        acc = make_float4(0.f, 0.f, 0.f, 0.f);
    }
    int e = g;
    for (; e + 12 < cnt; e += 16) {
        int s0 = row[e];
        int s1 = row[e + 4];
        int s2 = row[e + 8];
        int s3 = row[e + 12];
        float4 v0 = *reinterpret_cast<const float4*>(p + (size_t)s0 * F_HID + l * 4);
        float4 v1 = *reinterpret_cast<const float4*>(p + (size_t)s1 * F_HID + l * 4);
        float4 v2 = *reinterpret_cast<const float4*>(p + (size_t)s2 * F_HID + l * 4);
        float4 v3 = *reinterpret_cast<const float4*>(p + (size_t)s3 * F_HID + l * 4);
        acc.x += (v0.x + v1.x) + (v2.x + v3.x);
        acc.y += (v0.y + v1.y) + (v2.y + v3.y);
        acc.z += (v0.z + v1.z) + (v2.z + v3.z);
        acc.w += (v0.w + v1.w) + (v2.w + v3.w);
    }
    for (; e < cnt; e += 4) {
        int s = row[e];
        float4 v = *reinterpret_cast<const float4*>(p + (size_t)s * F_HID + l * 4);
        acc.x += v.x; acc.y += v.y; acc.z += v.z; acc.w += v.w;
    }
    // spill edges (normally zero; single cached load when empty)
    int nsp = g_spill_n;
    if (nsp > 0) {
        if (nsp > MAX_SPILL) nsp = MAX_SPILL;
        for (int i = g; i < nsp; i += 4) {
            int2 ed = g_spill[i];
            if (ed.x == n) {
                float4 v = *reinterpret_cast<const float4*>(p + (size_t)ed.y * F_HID + l * 4);
                acc.x += v.x; acc.y += v.y; acc.z += v.z; acc.w += v.w;
            }
        }
    }
    #pragma unroll
    for (int off = 8; off <= 16; off <<= 1) {
        acc.x += __shfl_xor_sync(0xffffffffu, acc.x, off);
        acc.y += __shfl_xor_sync(0xffffffffu, acc.y, off);
        acc.z += __shfl_xor_sync(0xffffffffu, acc.z, off);
        acc.w += __shfl_xor_sync(0xffffffffu, acc.w, off);
    }
    return redist32(acc, lane);
}

// ---------------- fused gather1 + node2 -------------------------------------
// a1 = gather(p1); r1 = relu(dis*a1 + b1); p2 = dis*(r1@W2[:32] + x@M2b + c2b)
__global__ void __launch_bounds__(256) k_gather_node2(const float* __restrict__ x,
                                                      const float* __restrict__ b1,
                                                      const float* __restrict__ W2)
{
    __shared__ float sW2t[F_HID * F_HID];
    __shared__ float sM2b[F_IN * F_HID];
    __shared__ float sc2b[F_HID];
    __shared__ float sb1[F_HID];
    for (int i = threadIdx.x; i < F_HID * F_HID; i += 256) sW2t[i] = W2[i];
    for (int i = threadIdx.x; i < F_IN * F_HID; i += 256) sM2b[i] = g_M2b[i];
    if (threadIdx.x < F_HID) { sc2b[threadIdx.x] = g_c2b[threadIdx.x];
                               sb1[threadIdx.x]  = b1[threadIdx.x]; }
    __syncthreads();

    int lane  = threadIdx.x & 31;
    int l     = lane & 7;
    int g     = lane >> 3;
    int warp  = (blockIdx.x * 256 + threadIdx.x) >> 5;
    int nwarp = (gridDim.x * 256) >> 5;

    for (int n = warp; n < N_NODES; n += nwarp) {
        float a1j = gather_node(g_p1, n, lane, l, g);
        float dis = g_dis[n];
        float r1  = fmaxf(dis * a1j + sb1[lane], 0.f);

        const float* xr = x + (size_t)n * F_IN;
        float acc = sc2b[lane];
        #pragma unroll
        for (int k = 0; k < F_IN; ++k)
            acc += xr[k] * sM2b[k * F_HID + lane];
        #pragma unroll
        for (int k = 0; k < F_HID; ++k) {
            float rk = __shfl_sync(0xffffffffu, r1, k);
            acc += rk * sW2t[k * F_HID + lane];
        }
        g_p2[(size_t)n * F_HID + lane] = dis * acc;
    }
}

// ---------------- fused gather2 + prediction --------------------------------
// a2 = gather(p2); r2 = relu(dis*a2 + b2);
// out = relu(r2@Wp[:32] + x@Mp + cp + bp + x[:,1])
__global__ void __launch_bounds__(256) k_gather_final(const float* __restrict__ x,
                                                      const float* __restrict__ b2,
                                                      const float* __restrict__ Wp,
                                                      const float* __restrict__ bp,
                                                      float* __restrict__ out)
{
    __shared__ float sb2[F_HID];
    __shared__ float swp[F_HID];
    __shared__ float sMp[F_IN];
    if (threadIdx.x < F_HID) { sb2[threadIdx.x] = b2[threadIdx.x];
                               swp[threadIdx.x] = Wp[threadIdx.x]; }
    if (threadIdx.x < F_IN) sMp[threadIdx.x] = g_Mp[threadIdx.x];
    __syncthreads();

    int lane  = threadIdx.x & 31;
    int l     = lane & 7;
    int g     = lane >> 3;
    int warp  = (blockIdx.x * 256 + threadIdx.x) >> 5;
    int nwarp = (gridDim.x * 256) >> 5;
    float bias = g_cp + bp[0];

    for (int n = warp; n < N_NODES; n += nwarp) {
        float a2j = gather_node(g_p2, n, lane, l, g);
        float dis = g_dis[n];
        float r2  = fmaxf(dis * a2j + sb2[lane], 0.f);

        const float* xr = x + (size_t)n * F_IN;
        float part = r2 * swp[lane];
        if (lane < F_IN) part += xr[lane] * sMp[lane];
        #pragma unroll
        for (int off = 16; off; off >>= 1)
            part += __shfl_xor_sync(0xffffffffu, part, off);
        if (lane == 0)
            out[n] = fmaxf(part + bias + xr[1], 0.f);
    }
}

// ---------------- launch ----------------------------------------------------
extern "C" void kernel_launch(void* const* d_in, const int* in_sizes, int n_in,
                              void* d_out, int out_size)
{
    const float* x   = (const float*)d_in[0];
    const void*  ei  = d_in[1];
    const float* We  = (const float*)d_in[2];
    const float* be  = (const float*)d_in[3];
    const float* W1  = (const float*)d_in[4];
    const float* b1  = (const float*)d_in[5];
    const float* W2  = (const float*)d_in[6];
    const float* b2  = (const float*)d_in[7];
    const float* Wp  = (const float*)d_in[8];
    const float* bp  = (const float*)d_in[9];
    float*       out = (float*)d_out;

    const int TB = 256;
    const int node1Blocks  = 2368;
    const int gatherBlocks = 2960;

    k_prep<<<ZERO_BLOCKS + 1, TB>>>(ei, We, be, W1, W2, Wp);
    k_place<<<PLACE_BLOCKS, TB>>>(ei);
    k_node1<<<node1Blocks, TB>>>(x);
    k_gather_node2<<<gatherBlocks, TB>>>(x, b1, W2);
    k_gather_final<<<gatherBlocks, TB>>>(x, b2, Wp, bp, out);
}